// round 4
// baseline (speedup 1.0000x reference)
#include <cuda_runtime.h>
#include <cuda_bf16.h>

// PointInstanceNorm: per-segment, per-channel instance norm over a ragged
// point cloud. x: [N, D] fp32 row-major; seqlen: [B+1] cumulative offsets;
// weight/bias: [D]. out[i,d] = (x[i,d]-mean[b,d]) * rsqrt(var[b,d]+eps) * w[d] + bias[d]
// where b = segment of row i.
//
// Strategy (HBM-bound, ~1.5GB min traffic):
//   K0: zero per-(b,d) accumulators
//   K1: read x once -> Sum and SumSq per (segment, channel) via block-partial
//       register accumulation + shared reduce + float atomicAdd
//   K2: finalize: scale = rsqrt(E[x^2]-mean^2 + eps)*w, shift = bias - mean*scale
//   K3: read x, out = fma(x, scale, shift), write out
//
// Blocks are 2D (chunk, segment): each block covers rows of exactly one
// segment (range computed on-device from seqlen), so no cross-segment logic.

#define PIN_EPS 1e-5f
#define PIN_MAXBD (1 << 20)   // max B*D supported by static scratch (4 MB/array)

__device__ float g_sum  [PIN_MAXBD];
__device__ float g_sq   [PIN_MAXBD];
__device__ float g_scale[PIN_MAXBD];
__device__ float g_shift[PIN_MAXBD];

__global__ void pin_zero_kernel(int n) {
    int i = blockIdx.x * blockDim.x + threadIdx.x;
    if (i < n) { g_sum[i] = 0.0f; g_sq[i] = 0.0f; }
}

// blockDim.x = 256. D must be divisible by 4; D4 = D/4 must satisfy D4 <= 256.
__global__ void pin_reduce_kernel(const float* __restrict__ x,
                                  const int*   __restrict__ seqlen,
                                  int D4) {
    const int b = blockIdx.y;
    const int s = seqlen[b];
    const int e = seqlen[b + 1];
    const int L = e - s;
    const int nb = gridDim.x;
    const int chunk = (L + nb - 1) / nb;
    long long r0 = (long long)s + (long long)blockIdx.x * chunk;
    long long r1 = (long long)s + (long long)min((long long)L,
                                                 (long long)(blockIdx.x + 1) * (long long)chunk);
    const int lane = threadIdx.x % D4;       // which float4 within the row
    const int grp  = threadIdx.x / D4;       // row group
    const int ngrp = blockDim.x / D4;        // rows per iteration

    float4 sum = make_float4(0.f, 0.f, 0.f, 0.f);
    float4 sq  = make_float4(0.f, 0.f, 0.f, 0.f);

    if (grp < ngrp) {
        const float4* __restrict__ x4 = (const float4*)x;
        for (long long r = r0 + grp; r < r1; r += ngrp) {
            float4 v = x4[r * D4 + lane];
            sum.x += v.x; sum.y += v.y; sum.z += v.z; sum.w += v.w;
            sq.x  += v.x * v.x; sq.y += v.y * v.y;
            sq.z  += v.z * v.z; sq.w += v.w * v.w;
        }
    }

    __shared__ float4 s_sum[256];
    __shared__ float4 s_sq [256];
    s_sum[threadIdx.x] = sum;
    s_sq [threadIdx.x] = sq;
    __syncthreads();

    if (grp == 0) {
        for (int g = 1; g < ngrp; g++) {
            float4 a = s_sum[g * D4 + lane];
            float4 c = s_sq [g * D4 + lane];
            sum.x += a.x; sum.y += a.y; sum.z += a.z; sum.w += a.w;
            sq.x  += c.x; sq.y  += c.y; sq.z  += c.z; sq.w  += c.w;
        }
        const int base = b * (D4 * 4) + lane * 4;
        atomicAdd(&g_sum[base + 0], sum.x);
        atomicAdd(&g_sum[base + 1], sum.y);
        atomicAdd(&g_sum[base + 2], sum.z);
        atomicAdd(&g_sum[base + 3], sum.w);
        atomicAdd(&g_sq [base + 0], sq.x);
        atomicAdd(&g_sq [base + 1], sq.y);
        atomicAdd(&g_sq [base + 2], sq.z);
        atomicAdd(&g_sq [base + 3], sq.w);
    }
}

__global__ void pin_finalize_kernel(const int*   __restrict__ seqlen,
                                    const float* __restrict__ w,
                                    const float* __restrict__ bias,
                                    int B, int D) {
    int i = blockIdx.x * blockDim.x + threadIdx.x;
    if (i >= B * D) return;
    int b = i / D;
    int d = i - b * D;
    float cnt   = (float)(seqlen[b + 1] - seqlen[b]);
    float denom = fmaxf(cnt, 1.0f);
    float mean  = g_sum[i] / denom;
    float var   = g_sq[i] / denom - mean * mean;
    var = fmaxf(var, 0.0f);
    float inv = rsqrtf(var + PIN_EPS);
    float sc  = inv * w[d];
    g_scale[i] = sc;
    g_shift[i] = bias[d] - mean * sc;
}

__global__ void pin_norm_kernel(const float* __restrict__ x,
                                const int*   __restrict__ seqlen,
                                float*       __restrict__ out,
                                int D4) {
    const int b = blockIdx.y;
    const int s = seqlen[b];
    const int e = seqlen[b + 1];
    const int L = e - s;
    const int nb = gridDim.x;
    const int chunk = (L + nb - 1) / nb;
    long long r0 = (long long)s + (long long)blockIdx.x * chunk;
    long long r1 = (long long)s + (long long)min((long long)L,
                                                 (long long)(blockIdx.x + 1) * (long long)chunk);
    const int lane = threadIdx.x % D4;
    const int grp  = threadIdx.x / D4;
    const int ngrp = blockDim.x / D4;
    if (grp >= ngrp) return;

    const float4 sc = ((const float4*)g_scale)[b * D4 + lane];
    const float4 sh = ((const float4*)g_shift)[b * D4 + lane];
    const float4* __restrict__ x4 = (const float4*)x;
    float4* __restrict__ o4 = (float4*)out;

    for (long long r = r0 + grp; r < r1; r += ngrp) {
        float4 v = x4[r * D4 + lane];
        float4 o;
        o.x = fmaf(v.x, sc.x, sh.x);
        o.y = fmaf(v.y, sc.y, sh.y);
        o.z = fmaf(v.z, sc.z, sh.z);
        o.w = fmaf(v.w, sc.w, sh.w);
        o4[r * D4 + lane] = o;
    }
}

// Generic scalar fallback (any D). One thread per (row, channel) strided.
__global__ void pin_reduce_scalar(const float* __restrict__ x,
                                  const int*   __restrict__ seqlen,
                                  int D) {
    const int b = blockIdx.y;
    const int s = seqlen[b];
    const int e = seqlen[b + 1];
    const int L = e - s;
    const int nb = gridDim.x;
    const int chunk = (L + nb - 1) / nb;
    long long r0 = (long long)s + (long long)blockIdx.x * chunk;
    long long r1 = (long long)s + (long long)min((long long)L,
                                                 (long long)(blockIdx.x + 1) * (long long)chunk);
    for (int d = threadIdx.x; d < D; d += blockDim.x) {
        float sum = 0.f, sq = 0.f;
        for (long long r = r0; r < r1; r++) {
            float v = x[r * D + d];
            sum += v; sq += v * v;
        }
        atomicAdd(&g_sum[b * D + d], sum);
        atomicAdd(&g_sq [b * D + d], sq);
    }
}

__global__ void pin_norm_scalar(const float* __restrict__ x,
                                const int*   __restrict__ seqlen,
                                float*       __restrict__ out,
                                int D) {
    const int b = blockIdx.y;
    const int s = seqlen[b];
    const int e = seqlen[b + 1];
    const int L = e - s;
    const int nb = gridDim.x;
    const int chunk = (L + nb - 1) / nb;
    long long r0 = (long long)s + (long long)blockIdx.x * chunk;
    long long r1 = (long long)s + (long long)min((long long)L,
                                                 (long long)(blockIdx.x + 1) * (long long)chunk);
    for (long long r = r0; r < r1; r++) {
        for (int d = threadIdx.x; d < D; d += blockDim.x) {
            float v = x[r * D + d];
            out[r * D + d] = fmaf(v, g_scale[b * D + d], g_shift[b * D + d]);
        }
    }
}

extern "C" void kernel_launch(void* const* d_in, const int* in_sizes, int n_in,
                              void* d_out, int out_size) {
    const float* x      = (const float*)d_in[0];
    const int*   seqlen = (const int*)  d_in[1];
    const float* weight = (const float*)d_in[2];
    const float* bias   = (const float*)d_in[3];
    float*       out    = (float*)d_out;

    const int D = in_sizes[2];            // weight is [1, D]
    const int B = in_sizes[1] - 1;        // seqlen is [B+1]
    const long long N = (long long)in_sizes[0] / D;
    const int BD = B * D;

    // K0: zero accumulators
    {
        int threads = 256;
        int blocks = (BD + threads - 1) / threads;
        pin_zero_kernel<<<blocks, threads>>>(BD);
    }

    const int D4 = D / 4;
    const bool vec_ok = (D % 4 == 0) && (D4 >= 1) && (D4 <= 256);

    // Chunks per segment: aim for ~4096 total blocks for load balance.
    int chunks = (int)((4096 + B - 1) / B);
    if (chunks < 1) chunks = 1;
    // Don't massively over-subscribe tiny inputs.
    long long avg_rows = (N + B - 1) / B;
    if ((long long)chunks > avg_rows && avg_rows > 0) chunks = (int)avg_rows;
    if (chunks < 1) chunks = 1;

    dim3 grid(chunks, B);

    // K1: reduce
    if (vec_ok) {
        pin_reduce_kernel<<<grid, 256>>>(x, seqlen, D4);
    } else {
        pin_reduce_scalar<<<grid, 256>>>(x, seqlen, D);
    }

    // K2: finalize scale/shift
    {
        int threads = 256;
        int blocks = (BD + threads - 1) / threads;
        pin_finalize_kernel<<<blocks, threads>>>(seqlen, weight, bias, B, D);
    }

    // K3: normalize
    if (vec_ok) {
        pin_norm_kernel<<<grid, 256>>>(x, seqlen, out, D4);
    } else {
        pin_norm_scalar<<<grid, 256>>>(x, seqlen, out, D);
    }
}